// round 3
// baseline (speedup 1.0000x reference)
#include <cuda_runtime.h>
#include <cstdint>

// ---------------- problem constants ----------------
#define IN_CH   32
#define OUT_CH  64
#define KSZ     5
#define KTOT    25
#define KTOTAL  832            // 25*32 + 32 (root rows)
#define MAX_N   50176          // 1024 * 49 (scan chunking)
#define MAX_E   1700000
#define NPB     32             // nodes per block (fused kernel)
#define SROW    34             // padded node stride in smem acc
#define BK      64             // W chunk rows staged in smem

// smem: acc [832][34] + ws [64][64] + sinv[32]
#define SMEM_FLOATS (KTOTAL * SROW + BK * OUT_CH + 32)
#define SMEM_BYTES  (SMEM_FLOATS * 4)

// ---------------- scratch (device globals; no allocation allowed) ----------------
__device__ int    g_deg[MAX_N];
__device__ int    g_cnt[MAX_N];
__device__ int    g_ptr[MAX_N + 1];
__device__ float  g_invdeg[MAX_N];
__device__ float4 g_erec[MAX_E];     // {col, wi_base, f0, f1} (first two bit-cast ints)

// ---------------- f32x2 helpers ----------------
__device__ __forceinline__ unsigned long long pack_f32x2(float lo, float hi) {
    unsigned long long d;
    asm("mov.b64 %0, {%1, %2};" : "=l"(d) : "f"(lo), "f"(hi));
    return d;
}
__device__ __forceinline__ void fma_f32x2(unsigned long long& c,
                                          unsigned long long a,
                                          unsigned long long b) {
    asm("fma.rn.f32x2 %0, %1, %2, %3;" : "=l"(c) : "l"(a), "l"(b), "l"(c));
}
__device__ __forceinline__ void unpack_f32x2(unsigned long long d, float& lo, float& hi) {
    asm("mov.b64 {%0, %1}, %2;" : "=f"(lo), "=f"(hi) : "l"(d));
}

// ---------------- k0: zero counters ----------------
__global__ void zero_small_kernel() {
    int i = blockIdx.x * 256 + threadIdx.x;
    if (i < MAX_N) { g_deg[i] = 0; g_cnt[i] = 0; }
}

// ---------------- k1: degree histogram ----------------
__global__ void hist_kernel(const int* __restrict__ ei, int E) {
    int e = blockIdx.x * 256 + threadIdx.x;
    if (e < E) atomicAdd(&g_deg[ei[e]], 1);
}

// ---------------- k2: exclusive scan (CSR ptr) + invdeg ----------------
__global__ void scan_kernel() {
    __shared__ int ssum[1024];
    const int C = MAX_N / 1024;   // 49
    int t = threadIdx.x;
    int base = t * C;
    int s = 0;
    for (int i = 0; i < C; ++i) s += g_deg[base + i];
    ssum[t] = s;
    __syncthreads();
    for (int off = 1; off < 1024; off <<= 1) {
        int v = (t >= off) ? ssum[t - off] : 0;
        __syncthreads();
        ssum[t] += v;
        __syncthreads();
    }
    int run = ssum[t] - s;   // exclusive prefix for this chunk
    for (int i = 0; i < C; ++i) {
        int idx = base + i;
        g_ptr[idx] = run;
        int d = g_deg[idx];
        run += d;
        g_invdeg[idx] = 1.0f / (float)max(d, 1);
    }
    if (t == 1023) g_ptr[MAX_N] = run;
}

// ---------------- k3: permute edges into CSR order ----------------
__global__ void permute_kernel(const int* __restrict__ ei,
                               const float* __restrict__ pseudo,
                               int E) {
    int e = blockIdx.x * 256 + threadIdx.x;
    if (e >= E) return;
    int row = ei[e];
    int col = ei[E + e];
    float2 ps = reinterpret_cast<const float2*>(pseudo)[e];
    float v0 = ps.x * 4.0f;           // (ks - open) = 4, v in [0,4)
    float v1 = ps.y * 4.0f;
    float b0 = floorf(v0), b1 = floorf(v1);
    float f0 = v0 - b0,  f1 = v1 - b1;
    int wib = (int)b0 + KSZ * (int)b1;
    int pos = g_ptr[row] + atomicAdd(&g_cnt[row], 1);
    g_erec[pos] = make_float4(__int_as_float(col), __int_as_float(wib), f0, f1);
}

// ---------------- fused: smem accumulate + GEMM ----------------
__global__ __launch_bounds__(256) void fused_kernel(const float* __restrict__ x,
                                                    const float* __restrict__ weight,
                                                    const float* __restrict__ bias,
                                                    float* __restrict__ out,
                                                    int N) {
    extern __shared__ float sm[];
    float* as   = sm;                         // [832][SROW]
    float* ws   = sm + KTOTAL * SROW;         // [BK][64]
    float* sinv = ws + BK * OUT_CH;           // [32]

    int tid  = threadIdx.x;
    int lane = tid & 31;
    int wid  = tid >> 5;
    int n0   = blockIdx.x * NPB;

    // ---- zero spline rows (kg 0..799) ----
    {
        float4 z = make_float4(0.f, 0.f, 0.f, 0.f);
        float4* a4 = reinterpret_cast<float4*>(as);
        const int n4 = (800 * SROW) / 4;      // SROW even -> divisible by 4? 800*34=27200, /4=6800
        for (int i = tid; i < n4; i += 256) a4[i] = z;
    }
    // ---- stage x into root rows (kg 800..831) ----
    for (int i = tid; i < NPB * IN_CH; i += 256) {
        int m = i >> 5, ch = i & 31;
        int n = n0 + m;
        float v = (n < N) ? x[(size_t)n * IN_CH + ch] : 0.f;
        as[(800 + ch) * SROW + m] = v;
    }
    if (tid < NPB) {
        int n = n0 + tid;
        sinv[tid] = (n < N) ? g_invdeg[n] : 0.f;
    }
    __syncthreads();

    // ---- accumulate edges (warp owns 4 nodes, no atomics) ----
    const int D = 32 * SROW;   // +1 in wi => +32 rows
    for (int nn = 0; nn < 4; ++nn) {
        int m = wid * 4 + nn;
        int n = n0 + m;
        if (n >= N) continue;
        int e   = g_ptr[n];
        int end = g_ptr[n + 1];
        if (e >= end) continue;

        float4 r[4];
#pragma unroll
        for (int j = 0; j < 4; ++j)
            r[j] = (e + j < end) ? __ldg(&g_erec[e + j]) : make_float4(0.f, 0.f, 0.f, 0.f);

        while (e < end) {
            int cnt = end - e; if (cnt > 4) cnt = 4;
            float xv[4];
#pragma unroll
            for (int j = 0; j < 4; ++j)
                if (j < cnt) {
                    int col = __float_as_int(r[j].x);
                    xv[j] = __ldg(&x[(size_t)col * IN_CH + lane]);
                }
            int e2 = e + 4;
            float4 rn[4];
#pragma unroll
            for (int j = 0; j < 4; ++j)
                rn[j] = (e2 + j < end) ? __ldg(&g_erec[e2 + j]) : make_float4(0.f, 0.f, 0.f, 0.f);
#pragma unroll
            for (int j = 0; j < 4; ++j)
                if (j < cnt) {
                    int  wib = __float_as_int(r[j].y);
                    float f0 = r[j].z, f1 = r[j].w;
                    float g0 = 1.f - f0, g1 = 1.f - f1;
                    int idx0 = (wib * 32 + lane) * SROW + m;
                    as[idx0]         += g0 * g1 * xv[j];
                    as[idx0 + D]     += f0 * g1 * xv[j];
                    as[idx0 + 5 * D] += g0 * f1 * xv[j];
                    as[idx0 + 6 * D] += f0 * f1 * xv[j];
                }
#pragma unroll
            for (int j = 0; j < 4; ++j) r[j] = rn[j];
            e = e2;
        }
    }
    __syncthreads();

    // ---- scale spline rows by 1/deg ----
    for (int i = tid; i < 800 * 32; i += 256) {
        int kg = i >> 5, m = i & 31;
        as[kg * SROW + m] *= sinv[m];
    }
    __syncthreads();

    // ---- GEMM: out[32 x 64] = as[832 x 32]^T @ W[832 x 64] ----
    int cx = tid & 31;          // col pair: cols 2cx, 2cx+1
    int my = tid >> 5;          // m base = 4*my
    int mb = 4 * my;

    unsigned long long acc00 = pack_f32x2(0.f, 0.f);
    unsigned long long acc10 = acc00, acc01 = acc00, acc11 = acc00;

    for (int kt = 0; kt < KTOTAL / BK; ++kt) {
        // stage W chunk
#pragma unroll
        for (int p = 0; p < 4; ++p) {
            int rrow = (tid >> 4) + 16 * p;
            int c4   = tid & 15;
            reinterpret_cast<float4*>(ws)[rrow * 16 + c4] =
                reinterpret_cast<const float4*>(weight)[(size_t)(kt * BK + rrow) * 16 + c4];
        }
        __syncthreads();
#pragma unroll 4
        for (int k = 0; k < BK; ++k) {
            int kg = kt * BK + k;
            unsigned long long a0 = *reinterpret_cast<unsigned long long*>(&as[kg * SROW + mb]);
            unsigned long long a1 = *reinterpret_cast<unsigned long long*>(&as[kg * SROW + mb + 2]);
            float w0 = ws[k * OUT_CH + 2 * cx];
            float w1 = ws[k * OUT_CH + 2 * cx + 1];
            unsigned long long wp0 = pack_f32x2(w0, w0);
            unsigned long long wp1 = pack_f32x2(w1, w1);
            fma_f32x2(acc00, a0, wp0);
            fma_f32x2(acc10, a1, wp0);
            fma_f32x2(acc01, a0, wp1);
            fma_f32x2(acc11, a1, wp1);
        }
        __syncthreads();
    }

    // ---- epilogue ----
    float bb0 = __ldg(&bias[2 * cx]);
    float bb1 = __ldg(&bias[2 * cx + 1]);
    float o00, o10, o20, o30, o01, o11, o21, o31;
    unpack_f32x2(acc00, o00, o10);   // (m, m+1) @ col c0
    unpack_f32x2(acc10, o20, o30);   // (m+2, m+3) @ col c0
    unpack_f32x2(acc01, o01, o11);   // (m, m+1) @ col c1
    unpack_f32x2(acc11, o21, o31);   // (m+2, m+3) @ col c1

    float2 rows[4] = {
        make_float2(o00 + bb0, o01 + bb1),
        make_float2(o10 + bb0, o11 + bb1),
        make_float2(o20 + bb0, o21 + bb1),
        make_float2(o30 + bb0, o31 + bb1)
    };
#pragma unroll
    for (int p = 0; p < 4; ++p) {
        int n = n0 + mb + p;
        if (n < N)
            *reinterpret_cast<float2*>(&out[(size_t)n * OUT_CH + 2 * cx]) = rows[p];
    }
}

// ---------------- launch ----------------
extern "C" void kernel_launch(void* const* d_in, const int* in_sizes, int n_in,
                              void* d_out, int out_size) {
    const float* x      = (const float*)d_in[0];
    const float* pseudo = (const float*)d_in[1];
    const int*   ei     = (const int*)  d_in[2];
    const float* weight = (const float*)d_in[3];
    const float* bias   = (const float*)d_in[4];
    float* out = (float*)d_out;

    int N = in_sizes[0] / IN_CH;
    int E = in_sizes[1] / 2;

    cudaFuncSetAttribute(fused_kernel, cudaFuncAttributeMaxDynamicSharedMemorySize, SMEM_BYTES);

    zero_small_kernel<<<(MAX_N + 255) / 256, 256>>>();
    hist_kernel<<<(E + 255) / 256, 256>>>(ei, E);
    scan_kernel<<<1, 1024>>>();
    permute_kernel<<<(E + 255) / 256, 256>>>(ei, pseudo, E);
    fused_kernel<<<(N + NPB - 1) / NPB, 256, SMEM_BYTES>>>(x, weight, bias, out, N);
}

// round 5
// speedup vs baseline: 1.0402x; 1.0402x over previous
#include <cuda_runtime.h>
#include <cstdint>

// ---------------- problem constants ----------------
#define IN_CH   32
#define OUT_CH  64
#define KSZ     5
#define KTOT    25
#define KTOTAL  832            // 25*32 + 32 (root rows)
#define MAX_N   50176          // 1024 * 49 (scan chunking)
#define MAX_E   1700000
#define NPB     32             // nodes per block (fused kernel)
#define SROW    34             // padded node stride in smem acc
#define BK      64             // W chunk rows staged in smem

// smem: acc [832][34] + ws [64][64] + sinv[32]
#define SMEM_FLOATS (KTOTAL * SROW + BK * OUT_CH + 32)
#define SMEM_BYTES  (SMEM_FLOATS * 4)

// ---------------- scratch (device globals; no allocation allowed) ----------------
__device__ int    g_deg[MAX_N];
__device__ int    g_cnt[MAX_N];
__device__ int    g_ptr[MAX_N + 1];
__device__ float  g_invdeg[MAX_N];
__device__ float4 g_erec[MAX_E];     // {col, wi_base, f0, f1} (first two bit-cast ints)

// ---------------- f32x2 helpers ----------------
__device__ __forceinline__ unsigned long long pack_f32x2(float lo, float hi) {
    unsigned long long d;
    asm("mov.b64 %0, {%1, %2};" : "=l"(d) : "f"(lo), "f"(hi));
    return d;
}
__device__ __forceinline__ void fma_f32x2(unsigned long long& c,
                                          unsigned long long a,
                                          unsigned long long b) {
    asm("fma.rn.f32x2 %0, %1, %2, %3;" : "=l"(c) : "l"(a), "l"(b), "l"(c));
}
__device__ __forceinline__ void unpack_f32x2(unsigned long long d, float& lo, float& hi) {
    asm("mov.b64 {%0, %1}, %2;" : "=f"(lo), "=f"(hi) : "l"(d));
}

// ---------------- k0: zero counters ----------------
__global__ void zero_small_kernel() {
    int i = blockIdx.x * 256 + threadIdx.x;
    if (i < MAX_N) { g_deg[i] = 0; g_cnt[i] = 0; }
}

// ---------------- k1: degree histogram ----------------
__global__ void hist_kernel(const int* __restrict__ ei, int E) {
    int e = blockIdx.x * 256 + threadIdx.x;
    if (e < E) atomicAdd(&g_deg[ei[e]], 1);
}

// ---------------- k2: exclusive scan (CSR ptr) + invdeg ----------------
__global__ void scan_kernel() {
    __shared__ int ssum[1024];
    const int C = MAX_N / 1024;   // 49
    int t = threadIdx.x;
    int base = t * C;
    int s = 0;
    for (int i = 0; i < C; ++i) s += g_deg[base + i];
    ssum[t] = s;
    __syncthreads();
    for (int off = 1; off < 1024; off <<= 1) {
        int v = (t >= off) ? ssum[t - off] : 0;
        __syncthreads();
        ssum[t] += v;
        __syncthreads();
    }
    int run = ssum[t] - s;   // exclusive prefix for this chunk
    for (int i = 0; i < C; ++i) {
        int idx = base + i;
        g_ptr[idx] = run;
        int d = g_deg[idx];
        run += d;
        g_invdeg[idx] = 1.0f / (float)max(d, 1);
    }
    if (t == 1023) g_ptr[MAX_N] = run;
}

// ---------------- k3: permute edges into CSR order ----------------
__global__ void permute_kernel(const int* __restrict__ ei,
                               const float* __restrict__ pseudo,
                               int E) {
    int e = blockIdx.x * 256 + threadIdx.x;
    if (e >= E) return;
    int row = ei[e];
    int col = ei[E + e];
    float2 ps = reinterpret_cast<const float2*>(pseudo)[e];
    float v0 = ps.x * 4.0f;           // (ks - open) = 4, v in [0,4)
    float v1 = ps.y * 4.0f;
    float b0 = floorf(v0), b1 = floorf(v1);
    float f0 = v0 - b0,  f1 = v1 - b1;
    int wib = (int)b0 + KSZ * (int)b1;
    int pos = g_ptr[row] + atomicAdd(&g_cnt[row], 1);
    g_erec[pos] = make_float4(__int_as_float(col), __int_as_float(wib), f0, f1);
}

// ---------------- fused: smem accumulate + GEMM ----------------
// acc layout: as[kg][m], kg in [0,832), m in [0,32) node-in-block, stride SROW.
// Rows 0..799: spline accumulator. Rows 800..831: x * deg (degree folded so the
// whole GEMM result can be scaled by 1/deg in the epilogue).
__global__ __launch_bounds__(256) void fused_kernel(const float* __restrict__ x,
                                                    const float* __restrict__ weight,
                                                    const float* __restrict__ bias,
                                                    float* __restrict__ out,
                                                    int N) {
    extern __shared__ float sm[];
    float* as   = sm;                         // [832][SROW]
    float* ws   = sm + KTOTAL * SROW;         // [BK][64]
    float* sinv = ws + BK * OUT_CH;           // [32]

    int tid  = threadIdx.x;
    int lane = tid & 31;
    int wid  = tid >> 5;
    int n0   = blockIdx.x * NPB;

    // ---- zero spline rows (kg 0..799) ----
    {
        float4 z = make_float4(0.f, 0.f, 0.f, 0.f);
        float4* a4 = reinterpret_cast<float4*>(as);
        const int n4 = (800 * SROW) / 4;      // 6800
        for (int i = tid; i < n4; i += 256) a4[i] = z;
    }
    if (tid < NPB) {
        int n = n0 + tid;
        sinv[tid] = (n < N) ? g_invdeg[n] : 1.f;
    }
    // ---- stage x * deg into root rows (kg 800..831) ----
    for (int i = tid; i < NPB * IN_CH; i += 256) {
        int m = i >> 5, ch = i & 31;
        int n = n0 + m;
        float v = 0.f;
        if (n < N) {
            float degf = (float)max(g_deg[n], 1);
            v = x[(size_t)n * IN_CH + ch] * degf;
        }
        as[(800 + ch) * SROW + m] = v;
    }
    __syncthreads();

    // ---- accumulate edges (warp owns 4 nodes, no atomics) ----
    const int D = 32 * SROW;   // +1 in wi => +32 rows
    for (int nn = 0; nn < 4; ++nn) {
        int m = wid * 4 + nn;
        int n = n0 + m;
        if (n >= N) continue;
        int e   = g_ptr[n];
        int end = g_ptr[n + 1];
        if (e >= end) continue;

        float4 r[4];
#pragma unroll
        for (int j = 0; j < 4; ++j)
            r[j] = (e + j < end) ? __ldg(&g_erec[e + j]) : make_float4(0.f, 0.f, 0.f, 0.f);

        while (e < end) {
            int cnt = end - e; if (cnt > 4) cnt = 4;
            float xv[4];
#pragma unroll
            for (int j = 0; j < 4; ++j)
                if (j < cnt) {
                    int col = __float_as_int(r[j].x);
                    xv[j] = __ldg(&x[(size_t)col * IN_CH + lane]);
                }
            int e2 = e + 4;
            float4 rn[4];
#pragma unroll
            for (int j = 0; j < 4; ++j)
                rn[j] = (e2 + j < end) ? __ldg(&g_erec[e2 + j]) : make_float4(0.f, 0.f, 0.f, 0.f);
#pragma unroll
            for (int j = 0; j < 4; ++j)
                if (j < cnt) {
                    int  wib = __float_as_int(r[j].y);
                    float f0 = r[j].z, f1 = r[j].w;
                    float g0 = 1.f - f0, g1 = 1.f - f1;
                    int idx0 = (wib * 32 + lane) * SROW + m;
                    as[idx0]         += g0 * g1 * xv[j];
                    as[idx0 + D]     += f0 * g1 * xv[j];
                    as[idx0 + 5 * D] += g0 * f1 * xv[j];
                    as[idx0 + 6 * D] += f0 * f1 * xv[j];
                }
#pragma unroll
            for (int j = 0; j < 4; ++j) r[j] = rn[j];
            e = e2;
        }
    }
    __syncthreads();

    // ---- GEMM: tmp[32 x 64] = as[832 x 32]^T @ W[832 x 64] ----
    int cx = tid & 31;          // col pair: cols 2cx, 2cx+1
    int my = tid >> 5;          // m base = 4*my
    int mb = 4 * my;

    unsigned long long acc00 = pack_f32x2(0.f, 0.f);
    unsigned long long acc10 = acc00, acc01 = acc00, acc11 = acc00;

    for (int kt = 0; kt < KTOTAL / BK; ++kt) {
        // stage W chunk
#pragma unroll
        for (int p = 0; p < 4; ++p) {
            int rrow = (tid >> 4) + 16 * p;
            int c4   = tid & 15;
            reinterpret_cast<float4*>(ws)[rrow * 16 + c4] =
                reinterpret_cast<const float4*>(weight)[(size_t)(kt * BK + rrow) * 16 + c4];
        }
        __syncthreads();
#pragma unroll 4
        for (int k = 0; k < BK; ++k) {
            int kg = kt * BK + k;
            unsigned long long a0 = *reinterpret_cast<unsigned long long*>(&as[kg * SROW + mb]);
            unsigned long long a1 = *reinterpret_cast<unsigned long long*>(&as[kg * SROW + mb + 2]);
            float w0 = ws[k * OUT_CH + 2 * cx];
            float w1 = ws[k * OUT_CH + 2 * cx + 1];
            unsigned long long wp0 = pack_f32x2(w0, w0);
            unsigned long long wp1 = pack_f32x2(w1, w1);
            fma_f32x2(acc00, a0, wp0);
            fma_f32x2(acc10, a1, wp0);
            fma_f32x2(acc01, a0, wp1);
            fma_f32x2(acc11, a1, wp1);
        }
        __syncthreads();
    }

    // ---- epilogue: scale by 1/deg, + bias, store ----
    float bb0 = __ldg(&bias[2 * cx]);
    float bb1 = __ldg(&bias[2 * cx + 1]);
    float iv0 = sinv[mb], iv1 = sinv[mb + 1], iv2 = sinv[mb + 2], iv3 = sinv[mb + 3];

    float o00, o10, o20, o30, o01, o11, o21, o31;
    unpack_f32x2(acc00, o00, o10);   // (m, m+1) @ col c0
    unpack_f32x2(acc10, o20, o30);   // (m+2, m+3) @ col c0
    unpack_f32x2(acc01, o01, o11);   // (m, m+1) @ col c1
    unpack_f32x2(acc11, o21, o31);   // (m+2, m+3) @ col c1

    float2 rows[4] = {
        make_float2(o00 * iv0 + bb0, o01 * iv0 + bb1),
        make_float2(o10 * iv1 + bb0, o11 * iv1 + bb1),
        make_float2(o20 * iv2 + bb0, o21 * iv2 + bb1),
        make_float2(o30 * iv3 + bb0, o31 * iv3 + bb1)
    };
#pragma unroll
    for (int p = 0; p < 4; ++p) {
        int n = n0 + mb + p;
        if (n < N)
            *reinterpret_cast<float2*>(&out[(size_t)n * OUT_CH + 2 * cx]) = rows[p];
    }
}

// ---------------- launch ----------------
extern "C" void kernel_launch(void* const* d_in, const int* in_sizes, int n_in,
                              void* d_out, int out_size) {
    const float* x      = (const float*)d_in[0];
    const float* pseudo = (const float*)d_in[1];
    const int*   ei     = (const int*)  d_in[2];
    const float* weight = (const float*)d_in[3];
    const float* bias   = (const float*)d_in[4];
    float* out = (float*)d_out;

    int N = in_sizes[0] / IN_CH;
    int E = in_sizes[1] / 2;

    cudaFuncSetAttribute(fused_kernel, cudaFuncAttributeMaxDynamicSharedMemorySize, SMEM_BYTES);

    zero_small_kernel<<<(MAX_N + 255) / 256, 256>>>();
    hist_kernel<<<(E + 255) / 256, 256>>>(ei, E);
    scan_kernel<<<1, 1024>>>();
    permute_kernel<<<(E + 255) / 256, 256>>>(ei, pseudo, E);
    fused_kernel<<<(N + NPB - 1) / NPB, 256, SMEM_BYTES>>>(x, weight, bias, out, N);
}

// round 7
// speedup vs baseline: 1.3464x; 1.2944x over previous
#include <cuda_runtime.h>
#include <cstdint>

// ---------------- problem constants ----------------
#define IN_CH   32
#define OUT_CH  64
#define KSZ     5
#define KTOT    25
#define KTOTAL  832            // 25*32 + 32 (root rows)
#define MAX_N   50176          // 1024 * 49 (scan chunking)
#define MAX_E   1700000
#define NPB     16             // nodes per block (fused kernel)
#define SROW    18             // padded node stride in smem acc (even: 8B-aligned pairs)
#define BK      64             // W chunk rows staged in smem

// smem: acc [832][18] + ws [64][64] + sinv[16]
#define SMEM_FLOATS (KTOTAL * SROW + BK * OUT_CH + NPB)
#define SMEM_BYTES  (SMEM_FLOATS * 4)     // 76,352 B -> 2 blocks/SM

// ---------------- scratch (device globals; no allocation allowed) ----------------
__device__ int    g_deg[MAX_N];
__device__ int    g_cnt[MAX_N];
__device__ int    g_ptr[MAX_N + 1];
__device__ float  g_invdeg[MAX_N];
__device__ float4 g_erec[MAX_E];     // {col, wi_base, f0, f1} (first two bit-cast ints)

// ---------------- f32x2 helpers ----------------
__device__ __forceinline__ unsigned long long pack_f32x2(float lo, float hi) {
    unsigned long long d;
    asm("mov.b64 %0, {%1, %2};" : "=l"(d) : "f"(lo), "f"(hi));
    return d;
}
__device__ __forceinline__ void fma_f32x2(unsigned long long& c,
                                          unsigned long long a,
                                          unsigned long long b) {
    asm("fma.rn.f32x2 %0, %1, %2, %3;" : "=l"(c) : "l"(a), "l"(b), "l"(c));
}
__device__ __forceinline__ void unpack_f32x2(unsigned long long d, float& lo, float& hi) {
    asm("mov.b64 {%0, %1}, %2;" : "=f"(lo), "=f"(hi) : "l"(d));
}

// ---------------- k0: zero counters ----------------
__global__ void zero_small_kernel() {
    int i = blockIdx.x * 256 + threadIdx.x;
    if (i < MAX_N) { g_deg[i] = 0; g_cnt[i] = 0; }
}

// ---------------- k1: degree histogram ----------------
__global__ void hist_kernel(const int* __restrict__ ei, int E) {
    int e = blockIdx.x * 256 + threadIdx.x;
    if (e < E) atomicAdd(&g_deg[ei[e]], 1);
}

// ---------------- k2: exclusive scan (CSR ptr) + invdeg ----------------
__global__ void scan_kernel() {
    __shared__ int ssum[1024];
    const int C = MAX_N / 1024;   // 49
    int t = threadIdx.x;
    int base = t * C;
    int s = 0;
    for (int i = 0; i < C; ++i) s += g_deg[base + i];
    ssum[t] = s;
    __syncthreads();
    for (int off = 1; off < 1024; off <<= 1) {
        int v = (t >= off) ? ssum[t - off] : 0;
        __syncthreads();
        ssum[t] += v;
        __syncthreads();
    }
    int run = ssum[t] - s;   // exclusive prefix for this chunk
    for (int i = 0; i < C; ++i) {
        int idx = base + i;
        g_ptr[idx] = run;
        int d = g_deg[idx];
        run += d;
        g_invdeg[idx] = 1.0f / (float)max(d, 1);
    }
    if (t == 1023) g_ptr[MAX_N] = run;
}

// ---------------- k3: permute edges into CSR order ----------------
__global__ void permute_kernel(const int* __restrict__ ei,
                               const float* __restrict__ pseudo,
                               int E) {
    int e = blockIdx.x * 256 + threadIdx.x;
    if (e >= E) return;
    int row = ei[e];
    int col = ei[E + e];
    float2 ps = reinterpret_cast<const float2*>(pseudo)[e];
    float v0 = ps.x * 4.0f;           // (ks - open) = 4, v in [0,4)
    float v1 = ps.y * 4.0f;
    float b0 = floorf(v0), b1 = floorf(v1);
    float f0 = v0 - b0,  f1 = v1 - b1;
    int wib = (int)b0 + KSZ * (int)b1;
    int pos = g_ptr[row] + atomicAdd(&g_cnt[row], 1);
    g_erec[pos] = make_float4(__int_as_float(col), __int_as_float(wib), f0, f1);
}

// ---------------- fused: smem accumulate + GEMM ----------------
// acc layout: as[kg][m], kg in [0,832), m in [0,16) node-in-block, stride SROW.
// Rows 0..799: spline accumulator. Rows 800..831: x * deg (degree folded so the
// whole GEMM output can be scaled by 1/deg in the epilogue).
// 2 blocks/SM: accumulate (LSU-bound) of one block overlaps GEMM (FMA-bound)
// of the other.
__global__ __launch_bounds__(256, 2) void fused_kernel(const float* __restrict__ x,
                                                       const float* __restrict__ weight,
                                                       const float* __restrict__ bias,
                                                       float* __restrict__ out,
                                                       int N) {
    extern __shared__ float sm[];
    float* as   = sm;                         // [832][SROW]
    float* ws   = sm + KTOTAL * SROW;         // [BK][64]
    float* sinv = ws + BK * OUT_CH;           // [16]

    int tid  = threadIdx.x;
    int lane = tid & 31;
    int wid  = tid >> 5;
    int n0   = blockIdx.x * NPB;

    // ---- zero spline rows (kg 0..799) ----
    {
        float4 z = make_float4(0.f, 0.f, 0.f, 0.f);
        float4* a4 = reinterpret_cast<float4*>(as);
        const int n4 = (800 * SROW) / 4;      // 3600
        for (int i = tid; i < n4; i += 256) a4[i] = z;
    }
    if (tid < NPB) {
        int n = n0 + tid;
        sinv[tid] = (n < N) ? g_invdeg[n] : 1.f;
    }
    // ---- stage x * deg into root rows (kg 800..831) ----
    for (int i = tid; i < NPB * IN_CH; i += 256) {
        int m = i >> 5, ch = i & 31;
        int n = n0 + m;
        float v = 0.f;
        if (n < N) {
            float degf = (float)max(g_deg[n], 1);
            v = x[(size_t)n * IN_CH + ch] * degf;
        }
        as[(800 + ch) * SROW + m] = v;
    }
    __syncthreads();

    // ---- accumulate edges (warp owns 2 nodes, no atomics) ----
    const int D = 32 * SROW;   // +1 in wi => +32 rows
#pragma unroll
    for (int nn = 0; nn < 2; ++nn) {
        int m = wid * 2 + nn;
        int n = n0 + m;
        if (n >= N) continue;
        int e   = g_ptr[n];
        int end = g_ptr[n + 1];
        if (e >= end) continue;

        float4 r[4];
#pragma unroll
        for (int j = 0; j < 4; ++j)
            r[j] = (e + j < end) ? __ldg(&g_erec[e + j]) : make_float4(0.f, 0.f, 0.f, 0.f);

        while (e < end) {
            int cnt = end - e; if (cnt > 4) cnt = 4;
            float xv[4];
#pragma unroll
            for (int j = 0; j < 4; ++j)
                if (j < cnt) {
                    int col = __float_as_int(r[j].x);
                    xv[j] = __ldg(&x[(size_t)col * IN_CH + lane]);
                }
            int e2 = e + 4;
            float4 rn[4];
#pragma unroll
            for (int j = 0; j < 4; ++j)
                rn[j] = (e2 + j < end) ? __ldg(&g_erec[e2 + j]) : make_float4(0.f, 0.f, 0.f, 0.f);
#pragma unroll
            for (int j = 0; j < 4; ++j)
                if (j < cnt) {
                    int  wib = __float_as_int(r[j].y);
                    float f0 = r[j].z, f1 = r[j].w;
                    float g0 = 1.f - f0, g1 = 1.f - f1;
                    int idx0 = (wib * 32 + lane) * SROW + m;
                    as[idx0]         += g0 * g1 * xv[j];
                    as[idx0 + D]     += f0 * g1 * xv[j];
                    as[idx0 + 5 * D] += g0 * f1 * xv[j];
                    as[idx0 + 6 * D] += f0 * f1 * xv[j];
                }
#pragma unroll
            for (int j = 0; j < 4; ++j) r[j] = rn[j];
            e = e2;
        }
    }
    __syncthreads();

    // ---- GEMM: tmp[16 x 64] = as[832 x 16]^T @ W[832 x 64] ----
    // Compute on threads 0..127 (4 rows x 2 cols each); ALL threads stage W and
    // hit the barriers so the CTA stays convergent.
    int cx = tid & 31;          // col pair: cols 2cx, 2cx+1
    int my = (tid >> 5) & 3;    // row slot (valid for tid < 128)
    int mb = 4 * my;
    bool compute = (tid < 128);

    unsigned long long acc00 = pack_f32x2(0.f, 0.f);
    unsigned long long acc10 = acc00, acc01 = acc00, acc11 = acc00;

    for (int kt = 0; kt < KTOTAL / BK; ++kt) {
        // stage W chunk (all 256 threads)
#pragma unroll
        for (int p = 0; p < 4; ++p) {
            int rrow = (tid >> 4) + 16 * p;
            int c4   = tid & 15;
            reinterpret_cast<float4*>(ws)[rrow * 16 + c4] =
                reinterpret_cast<const float4*>(weight)[(size_t)(kt * BK + rrow) * 16 + c4];
        }
        __syncthreads();
        if (compute) {
#pragma unroll 4
            for (int k = 0; k < BK; ++k) {
                int kg = kt * BK + k;
                unsigned long long a0 = *reinterpret_cast<unsigned long long*>(&as[kg * SROW + mb]);
                unsigned long long a1 = *reinterpret_cast<unsigned long long*>(&as[kg * SROW + mb + 2]);
                float w0 = ws[k * OUT_CH + 2 * cx];
                float w1 = ws[k * OUT_CH + 2 * cx + 1];
                unsigned long long wp0 = pack_f32x2(w0, w0);
                unsigned long long wp1 = pack_f32x2(w1, w1);
                fma_f32x2(acc00, a0, wp0);
                fma_f32x2(acc10, a1, wp0);
                fma_f32x2(acc01, a0, wp1);
                fma_f32x2(acc11, a1, wp1);
            }
        }
        __syncthreads();
    }

    // ---- epilogue: scale by 1/deg, + bias, store ----
    if (compute) {
        float bb0 = __ldg(&bias[2 * cx]);
        float bb1 = __ldg(&bias[2 * cx + 1]);
        float iv0 = sinv[mb], iv1 = sinv[mb + 1], iv2 = sinv[mb + 2], iv3 = sinv[mb + 3];

        float o00, o10, o20, o30, o01, o11, o21, o31;
        unpack_f32x2(acc00, o00, o10);   // (m, m+1) @ col c0
        unpack_f32x2(acc10, o20, o30);   // (m+2, m+3) @ col c0
        unpack_f32x2(acc01, o01, o11);   // (m, m+1) @ col c1
        unpack_f32x2(acc11, o21, o31);   // (m+2, m+3) @ col c1

        float2 rows[4] = {
            make_float2(o00 * iv0 + bb0, o01 * iv0 + bb1),
            make_float2(o10 * iv1 + bb0, o11 * iv1 + bb1),
            make_float2(o20 * iv2 + bb0, o21 * iv2 + bb1),
            make_float2(o30 * iv3 + bb0, o31 * iv3 + bb1)
        };
#pragma unroll
        for (int p = 0; p < 4; ++p) {
            int n = n0 + mb + p;
            if (n < N)
                *reinterpret_cast<float2*>(&out[(size_t)n * OUT_CH + 2 * cx]) = rows[p];
        }
    }
}

// ---------------- launch ----------------
extern "C" void kernel_launch(void* const* d_in, const int* in_sizes, int n_in,
                              void* d_out, int out_size) {
    const float* x      = (const float*)d_in[0];
    const float* pseudo = (const float*)d_in[1];
    const int*   ei     = (const int*)  d_in[2];
    const float* weight = (const float*)d_in[3];
    const float* bias   = (const float*)d_in[4];
    float* out = (float*)d_out;

    int N = in_sizes[0] / IN_CH;
    int E = in_sizes[1] / 2;

    cudaFuncSetAttribute(fused_kernel, cudaFuncAttributeMaxDynamicSharedMemorySize, SMEM_BYTES);

    zero_small_kernel<<<(MAX_N + 255) / 256, 256>>>();
    hist_kernel<<<(E + 255) / 256, 256>>>(ei, E);
    scan_kernel<<<1, 1024>>>();
    permute_kernel<<<(E + 255) / 256, 256>>>(ei, pseudo, E);
    fused_kernel<<<(N + NPB - 1) / NPB, 256, SMEM_BYTES>>>(x, weight, bias, out, N);
}

// round 10
// speedup vs baseline: 1.4128x; 1.0493x over previous
#include <cuda_runtime.h>
#include <cstdint>

// ---------------- problem constants ----------------
#define IN_CH   32
#define OUT_CH  64
#define KSZ     5
#define KTOTAL  832            // 25*32 + 32 (root rows)
#define MAX_N   50176          // 196 * 256
#define NBLK_SC 196
#define MAX_E   1700000
#define NPB     16             // nodes per block
#define SROW    18             // padded node stride (even: LDS.64 pairs)

// smem: as[832][18] + ws[64][64] + sinv[16]
#define SMEM_FLOATS (KTOTAL * SROW + 64 * OUT_CH + NPB)
#define SMEM_BYTES  (SMEM_FLOATS * 4)     // 76,352 B -> 2 blocks/SM

// ---------------- scratch ----------------
__device__ int    g_deg[MAX_N];
__device__ int    g_cnt[MAX_N];
__device__ int    g_ptr[MAX_N];
__device__ int    g_bsum[256];
__device__ int    g_boff[256];
__device__ float  g_invdeg[MAX_N];
__device__ float4 g_erec[MAX_E];   // {col(int), wib|m<<8 (int), f0, f1}

// ---------------- f32x2 helpers ----------------
typedef unsigned long long ull;
__device__ __forceinline__ ull pack2(float lo, float hi) {
    ull d; asm("mov.b64 %0, {%1, %2};" : "=l"(d) : "f"(lo), "f"(hi)); return d;
}
__device__ __forceinline__ void fma2(ull& c, ull a, ull b) {
    asm("fma.rn.f32x2 %0, %1, %2, %3;" : "=l"(c) : "l"(a), "l"(b), "l"(c));
}
__device__ __forceinline__ ull add2(ull a, ull b) {
    ull d; asm("add.rn.f32x2 %0, %1, %2;" : "=l"(d) : "l"(a), "l"(b)); return d;
}
__device__ __forceinline__ void unpack2(ull d, float& lo, float& hi) {
    asm("mov.b64 {%0, %1}, %2;" : "=f"(lo), "=f"(hi) : "l"(d));
}

// ---------------- k0: zero counters ----------------
__global__ void zero_small_kernel() {
    int i = blockIdx.x * 256 + threadIdx.x;
    if (i < MAX_N) { g_deg[i] = 0; g_cnt[i] = 0; }
}

// ---------------- k1: degree histogram ----------------
__global__ void hist_kernel(const int* __restrict__ ei, int E) {
    int e = blockIdx.x * 256 + threadIdx.x;
    if (e < E) atomicAdd(&g_deg[ei[e]], 1);
}

// ---------------- k2a: per-block sums ----------------
__global__ void scan_a_kernel() {
    __shared__ int s[256];
    int tid = threadIdx.x;
    int i = blockIdx.x * 256 + tid;
    int d = g_deg[i];
    s[tid] = d; __syncthreads();
    for (int off = 128; off > 0; off >>= 1) {
        if (tid < off) s[tid] += s[tid + off];
        __syncthreads();
    }
    if (tid == 0) g_bsum[blockIdx.x] = s[0];
}

// ---------------- k2b: scan of block sums ----------------
__global__ void scan_b_kernel() {
    __shared__ int s[256];
    int tid = threadIdx.x;
    int v = (tid < NBLK_SC) ? g_bsum[tid] : 0;
    s[tid] = v; __syncthreads();
    for (int off = 1; off < 256; off <<= 1) {
        int t = (tid >= off) ? s[tid - off] : 0;
        __syncthreads();
        s[tid] += t;
        __syncthreads();
    }
    if (tid < NBLK_SC) g_boff[tid] = s[tid] - v;
}

// ---------------- k2c: per-block exclusive scan -> g_ptr ----------------
__global__ void scan_c_kernel() {
    __shared__ int s[256];
    int tid = threadIdx.x;
    int i = blockIdx.x * 256 + tid;
    int d = g_deg[i];
    s[tid] = d; __syncthreads();
    for (int off = 1; off < 256; off <<= 1) {
        int t = (tid >= off) ? s[tid - off] : 0;
        __syncthreads();
        s[tid] += t;
        __syncthreads();
    }
    g_ptr[i] = g_boff[blockIdx.x] + s[tid] - d;
    g_invdeg[i] = 1.0f / (float)max(d, 1);
}

// ---------------- k3: permute edges into CSR order ----------------
__global__ void permute_kernel(const int* __restrict__ ei,
                               const float* __restrict__ pseudo,
                               int E) {
    int e = blockIdx.x * 256 + threadIdx.x;
    if (e >= E) return;
    int row = ei[e];
    int col = ei[E + e];
    float2 ps = reinterpret_cast<const float2*>(pseudo)[e];
    float v0 = ps.x * 4.0f;           // (ks - open) = 4, v in [0,4)
    float v1 = ps.y * 4.0f;
    float b0 = floorf(v0), b1 = floorf(v1);
    float f0 = v0 - b0,  f1 = v1 - b1;
    int wib = (int)b0 + KSZ * (int)b1;
    int meta = wib | ((row & (NPB - 1)) << 8);
    int pos = g_ptr[row] + atomicAdd(&g_cnt[row], 1);
    g_erec[pos] = make_float4(__int_as_float(col), __int_as_float(meta), f0, f1);
}

// ---------------- fused: RED.shared accumulate + f32x2 GEMM ----------------
__global__ __launch_bounds__(256, 2) void fused_kernel(const float* __restrict__ x,
                                                       const float* __restrict__ weight,
                                                       const float* __restrict__ bias,
                                                       float* __restrict__ out,
                                                       int N) {
    extern __shared__ float sm[];
    float* as   = sm;                        // [832][SROW]
    float* ws   = sm + KTOTAL * SROW;        // [64][64]
    float* sinv = ws + 64 * OUT_CH;          // [16]

    int tid  = threadIdx.x;
    int lane = tid & 31;
    int wid  = tid >> 5;
    int n0   = blockIdx.x * NPB;

    // ---- zero spline rows (kg 0..799) ----
    {
        float4 z = make_float4(0.f, 0.f, 0.f, 0.f);
        float4* a4 = reinterpret_cast<float4*>(as);
        for (int i = tid; i < (800 * SROW) / 4; i += 256) a4[i] = z;
    }
    if (tid < NPB) {
        int n = n0 + tid;
        sinv[tid] = (n < N) ? g_invdeg[n] : 1.f;
    }
    // ---- stage x * deg into root rows (kg 800..831) ----
    for (int i = tid; i < NPB * IN_CH; i += 256) {
        int m = i >> 5, ch = i & 31;
        int n = n0 + m;
        float v = 0.f;
        if (n < N) v = x[(size_t)n * IN_CH + ch] * (float)max(g_deg[n], 1);
        as[(800 + ch) * SROW + m] = v;
    }
    __syncthreads();

    // ---- accumulate: balanced warp split over block's CSR range, RED.shared ----
    {
        int base = g_ptr[n0];
        int last = n0 + NPB;
        int end  = (last < MAX_N) ? g_ptr[last] : g_ptr[MAX_N - 1] + g_deg[MAX_N - 1];
        int len  = end - base;
        int lo = base + ((len * wid) >> 3);
        int hi = base + ((len * (wid + 1)) >> 3);

        float4 R0[4], R1[4];
        float xv0[4];
#pragma unroll
        for (int j = 0; j < 4; ++j) {
            R0[j] = (lo + j     < hi) ? __ldg(&g_erec[lo + j])     : make_float4(0.f,0.f,0.f,0.f);
            R1[j] = (lo + 4 + j < hi) ? __ldg(&g_erec[lo + 4 + j]) : make_float4(0.f,0.f,0.f,0.f);
        }
#pragma unroll
        for (int j = 0; j < 4; ++j)
            xv0[j] = (lo + j < hi)
                   ? __ldg(&x[(size_t)__float_as_int(R0[j].x) * IN_CH + lane]) : 0.f;

        for (int e = lo; e < hi; e += 4) {
            float xv1[4];
#pragma unroll
            for (int j = 0; j < 4; ++j)
                xv1[j] = (e + 4 + j < hi)
                       ? __ldg(&x[(size_t)__float_as_int(R1[j].x) * IN_CH + lane]) : 0.f;
            float4 R2[4];
#pragma unroll
            for (int j = 0; j < 4; ++j)
                R2[j] = (e + 8 + j < hi) ? __ldg(&g_erec[e + 8 + j])
                                         : make_float4(0.f,0.f,0.f,0.f);
            int cnt = hi - e; if (cnt > 4) cnt = 4;
#pragma unroll
            for (int j = 0; j < 4; ++j)
                if (j < cnt) {
                    int  meta = __float_as_int(R0[j].y);
                    int  wib  = meta & 255;
                    int  m    = meta >> 8;
                    float f0 = R0[j].z, f1 = R0[j].w;
                    float g0 = 1.f - f0, g1 = 1.f - f1;
                    float xv = xv0[j];
                    float* p = &as[(wib * 32 + lane) * SROW + m];
                    atomicAdd(p,                    g0 * g1 * xv);
                    atomicAdd(p +  32 * SROW,       f0 * g1 * xv);
                    atomicAdd(p + 160 * SROW,       g0 * f1 * xv);
                    atomicAdd(p + 192 * SROW,       f0 * f1 * xv);
                }
#pragma unroll
            for (int j = 0; j < 4; ++j) { R0[j] = R1[j]; R1[j] = R2[j]; xv0[j] = xv1[j]; }
        }
    }
    __syncthreads();

    // ---- GEMM: out[16 x 64] = as[832 x 16]^T @ W[832 x 64] ----
    // Warps 0..3 compute: (khalf = wid>>1) x (chalf = wid&1).
    // Thread tile 4 rows x 4 cols; a and w loaded as LDS.64 pairs (multicast).
    int khalf = wid >> 1;
    int chalf = wid & 1;
    int rg = lane >> 3, cp = lane & 7;
    int mb = 4 * rg;
    int cb = chalf * 32 + 4 * cp;
    bool compute = (wid < 4);

    ull acc[2][4];
#pragma unroll
    for (int a = 0; a < 2; ++a)
#pragma unroll
        for (int b = 0; b < 4; ++b) acc[a][b] = pack2(0.f, 0.f);

    for (int kt = 0; kt < 13; ++kt) {
        // stage W chunk (all 256 threads)
#pragma unroll
        for (int p = 0; p < 4; ++p) {
            int rrow = (tid >> 4) + 16 * p;
            int c4   = tid & 15;
            reinterpret_cast<float4*>(ws)[rrow * 16 + c4] =
                reinterpret_cast<const float4*>(weight)[(size_t)(kt * 64 + rrow) * 16 + c4];
        }
        __syncthreads();
        bool mine = compute && (khalf ? (kt >= 6) : (kt < 6));
        if (mine) {
            const float* ap = &as[(kt * 64) * SROW + mb];
            const float* wp = &ws[cb];
#pragma unroll 8
            for (int k = 0; k < 64; ++k) {
                ull a0 = *reinterpret_cast<const ull*>(ap);
                ull a1 = *reinterpret_cast<const ull*>(ap + 2);
                ull wq0 = *reinterpret_cast<const ull*>(wp);
                ull wq1 = *reinterpret_cast<const ull*>(wp + 2);
                ap += SROW; wp += OUT_CH;
                float w0, w1, w2, w3;
                unpack2(wq0, w0, w1); unpack2(wq1, w2, w3);
                ull d0 = pack2(w0, w0), d1 = pack2(w1, w1);
                ull d2 = pack2(w2, w2), d3 = pack2(w3, w3);
                fma2(acc[0][0], a0, d0); fma2(acc[1][0], a1, d0);
                fma2(acc[0][1], a0, d1); fma2(acc[1][1], a1, d1);
                fma2(acc[0][2], a0, d2); fma2(acc[1][2], a1, d2);
                fma2(acc[0][3], a0, d3); fma2(acc[1][3], a1, d3);
            }
        }
        __syncthreads();
    }

    // ---- combine k-halves via smem (reuse ws) ----
    ull* red = reinterpret_cast<ull*>(ws);
    if (compute && khalf == 1) {
        int idx = chalf * 32 + lane;
#pragma unroll
        for (int a = 0; a < 2; ++a)
#pragma unroll
            for (int b = 0; b < 4; ++b) red[idx * 8 + a * 4 + b] = acc[a][b];
    }
    __syncthreads();
    if (compute && khalf == 0) {
        int idx = chalf * 32 + lane;
#pragma unroll
        for (int a = 0; a < 2; ++a)
#pragma unroll
            for (int b = 0; b < 4; ++b)
                acc[a][b] = add2(acc[a][b], red[idx * 8 + a * 4 + b]);

        // ---- epilogue: 1/deg scale, + bias, store float4 per row ----
        float bb[4];
#pragma unroll
        for (int q = 0; q < 4; ++q) bb[q] = __ldg(&bias[cb + q]);
#pragma unroll
        for (int p = 0; p < 4; ++p) {
            int n = n0 + mb + p;
            if (n >= N) continue;
            float iv = sinv[mb + p];
            float o[4];
#pragma unroll
            for (int q = 0; q < 4; ++q) {
                float lo_, hi_;
                unpack2(acc[p >> 1][q], lo_, hi_);
                o[q] = ((p & 1) ? hi_ : lo_) * iv + bb[q];
            }
            *reinterpret_cast<float4*>(&out[(size_t)n * OUT_CH + cb]) =
                make_float4(o[0], o[1], o[2], o[3]);
        }
    }
}

// ---------------- launch ----------------
extern "C" void kernel_launch(void* const* d_in, const int* in_sizes, int n_in,
                              void* d_out, int out_size) {
    const float* x      = (const float*)d_in[0];
    const float* pseudo = (const float*)d_in[1];
    const int*   ei     = (const int*)  d_in[2];
    const float* weight = (const float*)d_in[3];
    const float* bias   = (const float*)d_in[4];
    float* out = (float*)d_out;

    int N = in_sizes[0] / IN_CH;
    int E = in_sizes[1] / 2;

    cudaFuncSetAttribute(fused_kernel, cudaFuncAttributeMaxDynamicSharedMemorySize, SMEM_BYTES);

    zero_small_kernel<<<(MAX_N + 255) / 256, 256>>>();
    hist_kernel<<<(E + 255) / 256, 256>>>(ei, E);
    scan_a_kernel<<<NBLK_SC, 256>>>();
    scan_b_kernel<<<1, 256>>>();
    scan_c_kernel<<<NBLK_SC, 256>>>();
    permute_kernel<<<(E + 255) / 256, 256>>>(ei, pseudo, E);
    fused_kernel<<<(N + NPB - 1) / NPB, 256, SMEM_BYTES>>>(x, weight, bias, out, N);
}

// round 11
// speedup vs baseline: 1.4646x; 1.0366x over previous
#include <cuda_runtime.h>
#include <cstdint>

// ---------------- problem constants ----------------
#define IN_CH   32
#define OUT_CH  64
#define KSZ     5
#define KTOTAL  832            // 25*32 + 32 (root rows)
#define MAX_N   50176          // 196 * 256
#define NBLK_SC 196
#define MAX_E   1700000
#define NPB     16             // nodes per block
#define SROW    18             // padded node stride (even: LDS.64 pairs)

// smem: as[832][18] + ws[64][64] + sinv[16]
#define SMEM_FLOATS (KTOTAL * SROW + 64 * OUT_CH + NPB)
#define SMEM_BYTES  (SMEM_FLOATS * 4)     // 76,352 B -> 2 blocks/SM

// ---------------- scratch ----------------
__device__ int    g_deg[MAX_N];
__device__ int    g_cnt[MAX_N];
__device__ int    g_ptr[MAX_N];
__device__ int    g_bsum[256];
__device__ int    g_boff[256];
__device__ float  g_invdeg[MAX_N];
__device__ float4 g_erec[MAX_E];   // {col(int), wib|m<<8 (int), f0, f1}

// ---------------- f32x2 helpers ----------------
typedef unsigned long long ull;
__device__ __forceinline__ ull pack2(float lo, float hi) {
    ull d; asm("mov.b64 %0, {%1, %2};" : "=l"(d) : "f"(lo), "f"(hi)); return d;
}
__device__ __forceinline__ void fma2(ull& c, ull a, ull b) {
    asm("fma.rn.f32x2 %0, %1, %2, %3;" : "=l"(c) : "l"(a), "l"(b), "l"(c));
}
__device__ __forceinline__ ull add2(ull a, ull b) {
    ull d; asm("add.rn.f32x2 %0, %1, %2;" : "=l"(d) : "l"(a), "l"(b)); return d;
}
__device__ __forceinline__ void unpack2(ull d, float& lo, float& hi) {
    asm("mov.b64 {%0, %1}, %2;" : "=f"(lo), "=f"(hi) : "l"(d));
}

// ---------------- k0: zero counters ----------------
__global__ void zero_small_kernel() {
    int i = blockIdx.x * 256 + threadIdx.x;
    if (i < MAX_N) { g_deg[i] = 0; g_cnt[i] = 0; }
}

// ---------------- k1: degree histogram ----------------
__global__ void hist_kernel(const int* __restrict__ ei, int E) {
    int e = blockIdx.x * 256 + threadIdx.x;
    if (e < E) atomicAdd(&g_deg[ei[e]], 1);
}

// ---------------- k2a: per-block sums ----------------
__global__ void scan_a_kernel() {
    __shared__ int s[256];
    int tid = threadIdx.x;
    int i = blockIdx.x * 256 + tid;
    int d = g_deg[i];
    s[tid] = d; __syncthreads();
    for (int off = 128; off > 0; off >>= 1) {
        if (tid < off) s[tid] += s[tid + off];
        __syncthreads();
    }
    if (tid == 0) g_bsum[blockIdx.x] = s[0];
}

// ---------------- k2b: scan of block sums ----------------
__global__ void scan_b_kernel() {
    __shared__ int s[256];
    int tid = threadIdx.x;
    int v = (tid < NBLK_SC) ? g_bsum[tid] : 0;
    s[tid] = v; __syncthreads();
    for (int off = 1; off < 256; off <<= 1) {
        int t = (tid >= off) ? s[tid - off] : 0;
        __syncthreads();
        s[tid] += t;
        __syncthreads();
    }
    if (tid < NBLK_SC) g_boff[tid] = s[tid] - v;
}

// ---------------- k2c: per-block exclusive scan -> g_ptr ----------------
__global__ void scan_c_kernel() {
    __shared__ int s[256];
    int tid = threadIdx.x;
    int i = blockIdx.x * 256 + tid;
    int d = g_deg[i];
    s[tid] = d; __syncthreads();
    for (int off = 1; off < 256; off <<= 1) {
        int t = (tid >= off) ? s[tid - off] : 0;
        __syncthreads();
        s[tid] += t;
        __syncthreads();
    }
    g_ptr[i] = g_boff[blockIdx.x] + s[tid] - d;
    g_invdeg[i] = 1.0f / (float)max(d, 1);
}

// ---------------- k3: permute edges into CSR order ----------------
__global__ void permute_kernel(const int* __restrict__ ei,
                               const float* __restrict__ pseudo,
                               int E) {
    int e = blockIdx.x * 256 + threadIdx.x;
    if (e >= E) return;
    int row = ei[e];
    int col = ei[E + e];
    float2 ps = reinterpret_cast<const float2*>(pseudo)[e];
    float v0 = ps.x * 4.0f;           // (ks - open) = 4, v in [0,4)
    float v1 = ps.y * 4.0f;
    float b0 = floorf(v0), b1 = floorf(v1);
    float f0 = v0 - b0,  f1 = v1 - b1;
    int wib = (int)b0 + KSZ * (int)b1;
    int meta = wib | ((row & (NPB - 1)) << 8);
    int pos = g_ptr[row] + atomicAdd(&g_cnt[row], 1);
    g_erec[pos] = make_float4(__int_as_float(col), __int_as_float(meta), f0, f1);
}

// ---------------- fused: race-free RMW accumulate + f32x2 GEMM ----------------
__global__ __launch_bounds__(256, 2) void fused_kernel(const float* __restrict__ x,
                                                       const float* __restrict__ weight,
                                                       const float* __restrict__ bias,
                                                       float* __restrict__ out,
                                                       int N) {
    extern __shared__ float sm[];
    float* as   = sm;                        // [832][SROW]
    float* ws   = sm + KTOTAL * SROW;        // [64][64]
    float* sinv = ws + 64 * OUT_CH;          // [16]

    int tid  = threadIdx.x;
    int lane = tid & 31;
    int wid  = tid >> 5;
    int n0   = blockIdx.x * NPB;

    // ---- zero spline rows (kg 0..799) ----
    {
        float4 z = make_float4(0.f, 0.f, 0.f, 0.f);
        float4* a4 = reinterpret_cast<float4*>(as);
        for (int i = tid; i < (800 * SROW) / 4; i += 256) a4[i] = z;
    }
    if (tid < NPB) {
        int n = n0 + tid;
        sinv[tid] = (n < N) ? g_invdeg[n] : 1.f;
    }
    // ---- stage x * deg into root rows (kg 800..831) ----
    for (int i = tid; i < NPB * IN_CH; i += 256) {
        int m = i >> 5, ch = i & 31;
        int n = n0 + m;
        float v = 0.f;
        if (n < N) v = x[(size_t)n * IN_CH + ch] * (float)max(g_deg[n], 1);
        as[(800 + ch) * SROW + m] = v;
    }
    __syncthreads();

    // ---- accumulate: warp owns 2 nodes, lane owns channel -> race-free RMW ----
#pragma unroll
    for (int nn = 0; nn < 2; ++nn) {
        int m = wid * 2 + nn;
        int n = n0 + m;
        if (n >= N) continue;
        int lo  = g_ptr[n];
        int hi  = g_ptr[n + 1];
        if (lo >= hi) continue;

        float4 R0[4], R1[4];
        float xv0[4];
#pragma unroll
        for (int j = 0; j < 4; ++j) {
            R0[j] = (lo + j     < hi) ? __ldg(&g_erec[lo + j])     : make_float4(0.f,0.f,0.f,0.f);
            R1[j] = (lo + 4 + j < hi) ? __ldg(&g_erec[lo + 4 + j]) : make_float4(0.f,0.f,0.f,0.f);
        }
#pragma unroll
        for (int j = 0; j < 4; ++j)
            xv0[j] = (lo + j < hi)
                   ? __ldg(&x[(size_t)__float_as_int(R0[j].x) * IN_CH + lane]) : 0.f;

        for (int e = lo; e < hi; e += 4) {
            float xv1[4];
#pragma unroll
            for (int j = 0; j < 4; ++j)
                xv1[j] = (e + 4 + j < hi)
                       ? __ldg(&x[(size_t)__float_as_int(R1[j].x) * IN_CH + lane]) : 0.f;
            float4 R2[4];
#pragma unroll
            for (int j = 0; j < 4; ++j)
                R2[j] = (e + 8 + j < hi) ? __ldg(&g_erec[e + 8 + j])
                                         : make_float4(0.f,0.f,0.f,0.f);
            int cnt = hi - e; if (cnt > 4) cnt = 4;
#pragma unroll
            for (int j = 0; j < 4; ++j)
                if (j < cnt) {
                    int  wib  = __float_as_int(R0[j].y) & 255;
                    float f0 = R0[j].z, f1 = R0[j].w;
                    float g0 = 1.f - f0, g1 = 1.f - f1;
                    float xv = xv0[j];
                    float* p = &as[(wib * 32 + lane) * SROW + m];
                    p[0]          += g0 * g1 * xv;     // LDS+FFMA+STS, no races
                    p[ 32 * SROW] += f0 * g1 * xv;
                    p[160 * SROW] += g0 * f1 * xv;
                    p[192 * SROW] += f0 * f1 * xv;
                }
#pragma unroll
            for (int j = 0; j < 4; ++j) { R0[j] = R1[j]; R1[j] = R2[j]; xv0[j] = xv1[j]; }
        }
    }
    __syncthreads();

    // ---- GEMM: out[16 x 64] = as[832 x 16]^T @ W[832 x 64] ----
    // Warps 0..3 compute: (khalf = wid>>1) x (chalf = wid&1).
    // W chunk double-buffered through registers: LDG for kt+1 issued before
    // computing kt, hiding L2 latency.
    int khalf = wid >> 1;
    int chalf = wid & 1;
    int rg = lane >> 3, cp = lane & 7;
    int mb = 4 * rg;
    int cb = chalf * 32 + 4 * cp;
    bool compute = (wid < 4);

    ull acc[2][4];
#pragma unroll
    for (int a = 0; a < 2; ++a)
#pragma unroll
        for (int b = 0; b < 4; ++b) acc[a][b] = pack2(0.f, 0.f);

    const int srow = (tid >> 4);       // 0..15
    const int sc4  = tid & 15;         // float4 col
    float4 wreg[4];
#pragma unroll
    for (int p = 0; p < 4; ++p)
        wreg[p] = reinterpret_cast<const float4*>(weight)[(size_t)(srow + 16 * p) * 16 + sc4];

    for (int kt = 0; kt < 13; ++kt) {
        // stage W chunk from registers (all 256 threads)
#pragma unroll
        for (int p = 0; p < 4; ++p)
            reinterpret_cast<float4*>(ws)[(srow + 16 * p) * 16 + sc4] = wreg[p];
        __syncthreads();
        // prefetch next chunk
        if (kt < 12) {
#pragma unroll
            for (int p = 0; p < 4; ++p)
                wreg[p] = reinterpret_cast<const float4*>(
                    weight)[(size_t)((kt + 1) * 64 + srow + 16 * p) * 16 + sc4];
        }
        bool mine = compute && (khalf ? (kt >= 6) : (kt < 6));
        if (mine) {
            const float* ap = &as[(kt * 64) * SROW + mb];
            const float* wp = &ws[cb];
#pragma unroll 8
            for (int k = 0; k < 64; ++k) {
                ull a0 = *reinterpret_cast<const ull*>(ap);
                ull a1 = *reinterpret_cast<const ull*>(ap + 2);
                ull wq0 = *reinterpret_cast<const ull*>(wp);
                ull wq1 = *reinterpret_cast<const ull*>(wp + 2);
                ap += SROW; wp += OUT_CH;
                float w0, w1, w2, w3;
                unpack2(wq0, w0, w1); unpack2(wq1, w2, w3);
                ull d0 = pack2(w0, w0), d1 = pack2(w1, w1);
                ull d2 = pack2(w2, w2), d3 = pack2(w3, w3);
                fma2(acc[0][0], a0, d0); fma2(acc[1][0], a1, d0);
                fma2(acc[0][1], a0, d1); fma2(acc[1][1], a1, d1);
                fma2(acc[0][2], a0, d2); fma2(acc[1][2], a1, d2);
                fma2(acc[0][3], a0, d3); fma2(acc[1][3], a1, d3);
            }
        }
        __syncthreads();
    }

    // ---- combine k-halves via smem (reuse ws) ----
    ull* red = reinterpret_cast<ull*>(ws);
    if (compute && khalf == 1) {
        int idx = chalf * 32 + lane;
#pragma unroll
        for (int a = 0; a < 2; ++a)
#pragma unroll
            for (int b = 0; b < 4; ++b) red[idx * 8 + a * 4 + b] = acc[a][b];
    }
    __syncthreads();
    if (compute && khalf == 0) {
        int idx = chalf * 32 + lane;
#pragma unroll
        for (int a = 0; a < 2; ++a)
#pragma unroll
            for (int b = 0; b < 4; ++b)
                acc[a][b] = add2(acc[a][b], red[idx * 8 + a * 4 + b]);

        // ---- epilogue: 1/deg scale, + bias, store float4 per row ----
        float bb[4];
#pragma unroll
        for (int q = 0; q < 4; ++q) bb[q] = __ldg(&bias[cb + q]);
#pragma unroll
        for (int p = 0; p < 4; ++p) {
            int n = n0 + mb + p;
            if (n >= N) continue;
            float iv = sinv[mb + p];
            float o[4];
#pragma unroll
            for (int q = 0; q < 4; ++q) {
                float lo_, hi_;
                unpack2(acc[p >> 1][q], lo_, hi_);
                o[q] = ((p & 1) ? hi_ : lo_) * iv + bb[q];
            }
            *reinterpret_cast<float4*>(&out[(size_t)n * OUT_CH + cb]) =
                make_float4(o[0], o[1], o[2], o[3]);
        }
    }
}

// ---------------- launch ----------------
extern "C" void kernel_launch(void* const* d_in, const int* in_sizes, int n_in,
                              void* d_out, int out_size) {
    const float* x      = (const float*)d_in[0];
    const float* pseudo = (const float*)d_in[1];
    const int*   ei     = (const int*)  d_in[2];
    const float* weight = (const float*)d_in[3];
    const float* bias   = (const float*)d_in[4];
    float* out = (float*)d_out;

    int N = in_sizes[0] / IN_CH;
    int E = in_sizes[1] / 2;

    cudaFuncSetAttribute(fused_kernel, cudaFuncAttributeMaxDynamicSharedMemorySize, SMEM_BYTES);

    zero_small_kernel<<<(MAX_N + 255) / 256, 256>>>();
    hist_kernel<<<(E + 255) / 256, 256>>>(ei, E);
    scan_a_kernel<<<NBLK_SC, 256>>>();
    scan_b_kernel<<<1, 256>>>();
    scan_c_kernel<<<NBLK_SC, 256>>>();
    permute_kernel<<<(E + 255) / 256, 256>>>(ei, pseudo, E);
    fused_kernel<<<(N + NPB - 1) / NPB, 256, SMEM_BYTES>>>(x, weight, bias, out, N);
}

// round 12
// speedup vs baseline: 1.4653x; 1.0005x over previous
#include <cuda_runtime.h>
#include <cstdint>

// ---------------- problem constants ----------------
#define IN_CH   32
#define OUT_CH  64
#define KSZ     5
#define KTOTAL  832            // 25*32 + 32 (root rows)
#define MAX_N   50176          // 196 * 256
#define NBLK_SC 196
#define MAX_E   1700000
#define NPB     16             // nodes per block
#define SROW    18             // padded node stride (even: LDS.64 pairs)

// smem: as[832][18] + ws[64][64] + sinv[16]
#define SMEM_FLOATS (KTOTAL * SROW + 64 * OUT_CH + NPB)
#define SMEM_BYTES  (SMEM_FLOATS * 4)     // 76,352 B -> 2 blocks/SM

// ---------------- scratch ----------------
__device__ int    g_deg[MAX_N];
__device__ int    g_cnt[MAX_N];
__device__ int    g_ptr[MAX_N];
__device__ int    g_bsum[256];
__device__ int    g_boff[256];
__device__ float  g_invdeg[MAX_N];
__device__ float4 g_erec[MAX_E];   // {col(int), wib|m<<8 (int), f0, f1}

// ---------------- f32x2 helpers ----------------
typedef unsigned long long ull;
__device__ __forceinline__ ull pack2(float lo, float hi) {
    ull d; asm("mov.b64 %0, {%1, %2};" : "=l"(d) : "f"(lo), "f"(hi)); return d;
}
__device__ __forceinline__ void fma2(ull& c, ull a, ull b) {
    asm("fma.rn.f32x2 %0, %1, %2, %3;" : "=l"(c) : "l"(a), "l"(b), "l"(c));
}
__device__ __forceinline__ ull add2(ull a, ull b) {
    ull d; asm("add.rn.f32x2 %0, %1, %2;" : "=l"(d) : "l"(a), "l"(b)); return d;
}
__device__ __forceinline__ void unpack2(ull d, float& lo, float& hi) {
    asm("mov.b64 {%0, %1}, %2;" : "=f"(lo), "=f"(hi) : "l"(d));
}

// ---------------- k0: zero counters ----------------
__global__ void zero_small_kernel() {
    int i = blockIdx.x * 256 + threadIdx.x;
    if (i < MAX_N) { g_deg[i] = 0; g_cnt[i] = 0; }
}

// ---------------- k1: degree histogram ----------------
__global__ void hist_kernel(const int* __restrict__ ei, int E) {
    int e = blockIdx.x * 256 + threadIdx.x;
    if (e < E) atomicAdd(&g_deg[ei[e]], 1);
}

// ---------------- k2a: per-block sums ----------------
__global__ void scan_a_kernel() {
    __shared__ int s[256];
    int tid = threadIdx.x;
    int i = blockIdx.x * 256 + tid;
    int d = g_deg[i];
    s[tid] = d; __syncthreads();
    for (int off = 128; off > 0; off >>= 1) {
        if (tid < off) s[tid] += s[tid + off];
        __syncthreads();
    }
    if (tid == 0) g_bsum[blockIdx.x] = s[0];
}

// ---------------- k2b: scan of block sums ----------------
__global__ void scan_b_kernel() {
    __shared__ int s[256];
    int tid = threadIdx.x;
    int v = (tid < NBLK_SC) ? g_bsum[tid] : 0;
    s[tid] = v; __syncthreads();
    for (int off = 1; off < 256; off <<= 1) {
        int t = (tid >= off) ? s[tid - off] : 0;
        __syncthreads();
        s[tid] += t;
        __syncthreads();
    }
    if (tid < NBLK_SC) g_boff[tid] = s[tid] - v;
}

// ---------------- k2c: per-block exclusive scan -> g_ptr ----------------
__global__ void scan_c_kernel() {
    __shared__ int s[256];
    int tid = threadIdx.x;
    int i = blockIdx.x * 256 + tid;
    int d = g_deg[i];
    s[tid] = d; __syncthreads();
    for (int off = 1; off < 256; off <<= 1) {
        int t = (tid >= off) ? s[tid - off] : 0;
        __syncthreads();
        s[tid] += t;
        __syncthreads();
    }
    g_ptr[i] = g_boff[blockIdx.x] + s[tid] - d;
    g_invdeg[i] = 1.0f / (float)max(d, 1);
}

// ---------------- k3: permute edges into CSR order ----------------
__global__ void permute_kernel(const int* __restrict__ ei,
                               const float* __restrict__ pseudo,
                               int E) {
    int e = blockIdx.x * 256 + threadIdx.x;
    if (e >= E) return;
    int row = ei[e];
    int col = ei[E + e];
    float2 ps = reinterpret_cast<const float2*>(pseudo)[e];
    float v0 = ps.x * 4.0f;           // (ks - open) = 4, v in [0,4)
    float v1 = ps.y * 4.0f;
    float b0 = floorf(v0), b1 = floorf(v1);
    float f0 = v0 - b0,  f1 = v1 - b1;
    int wib = (int)b0 + KSZ * (int)b1;
    int meta = wib | ((row & (NPB - 1)) << 8);
    int pos = g_ptr[row] + atomicAdd(&g_cnt[row], 1);
    g_erec[pos] = make_float4(__int_as_float(col), __int_as_float(meta), f0, f1);
}

// ---------------- fused: race-free RMW accumulate + f32x2 GEMM ----------------
__global__ __launch_bounds__(256, 2) void fused_kernel(const float* __restrict__ x,
                                                       const float* __restrict__ weight,
                                                       const float* __restrict__ bias,
                                                       float* __restrict__ out,
                                                       int N) {
    extern __shared__ float sm[];
    float* as   = sm;                        // [832][SROW]
    float* ws   = sm + KTOTAL * SROW;        // [64][64]
    float* sinv = ws + 64 * OUT_CH;          // [16]

    int tid  = threadIdx.x;
    int lane = tid & 31;
    int wid  = tid >> 5;
    int n0   = blockIdx.x * NPB;

    // ---- zero spline rows (kg 0..799) ----
    {
        float4 z = make_float4(0.f, 0.f, 0.f, 0.f);
        float4* a4 = reinterpret_cast<float4*>(as);
        for (int i = tid; i < (800 * SROW) / 4; i += 256) a4[i] = z;
    }
    if (tid < NPB) {
        int n = n0 + tid;
        sinv[tid] = (n < N) ? g_invdeg[n] : 1.f;
    }
    // ---- stage x * deg into root rows (kg 800..831) ----
    for (int i = tid; i < NPB * IN_CH; i += 256) {
        int m = i >> 5, ch = i & 31;
        int n = n0 + m;
        float v = 0.f;
        if (n < N) v = x[(size_t)n * IN_CH + ch] * (float)max(g_deg[n], 1);
        as[(800 + ch) * SROW + m] = v;
    }
    __syncthreads();

    // ---- accumulate: warp owns 2 nodes, lane owns channel -> race-free RMW ----
#pragma unroll
    for (int nn = 0; nn < 2; ++nn) {
        int m = wid * 2 + nn;
        int n = n0 + m;
        if (n >= N) continue;
        int lo  = g_ptr[n];
        int hi  = g_ptr[n + 1];
        if (lo >= hi) continue;

        float4 R0[4], R1[4];
        float xv0[4];
#pragma unroll
        for (int j = 0; j < 4; ++j) {
            R0[j] = (lo + j     < hi) ? __ldg(&g_erec[lo + j])     : make_float4(0.f,0.f,0.f,0.f);
            R1[j] = (lo + 4 + j < hi) ? __ldg(&g_erec[lo + 4 + j]) : make_float4(0.f,0.f,0.f,0.f);
        }
#pragma unroll
        for (int j = 0; j < 4; ++j)
            xv0[j] = (lo + j < hi)
                   ? __ldg(&x[(size_t)__float_as_int(R0[j].x) * IN_CH + lane]) : 0.f;

        for (int e = lo; e < hi; e += 4) {
            float xv1[4];
#pragma unroll
            for (int j = 0; j < 4; ++j)
                xv1[j] = (e + 4 + j < hi)
                       ? __ldg(&x[(size_t)__float_as_int(R1[j].x) * IN_CH + lane]) : 0.f;
            float4 R2[4];
#pragma unroll
            for (int j = 0; j < 4; ++j)
                R2[j] = (e + 8 + j < hi) ? __ldg(&g_erec[e + 8 + j])
                                         : make_float4(0.f,0.f,0.f,0.f);
            int cnt = hi - e; if (cnt > 4) cnt = 4;
#pragma unroll
            for (int j = 0; j < 4; ++j)
                if (j < cnt) {
                    int  wib  = __float_as_int(R0[j].y) & 255;
                    float f0 = R0[j].z, f1 = R0[j].w;
                    float g0 = 1.f - f0, g1 = 1.f - f1;
                    float xv = xv0[j];
                    float* p = &as[(wib * 32 + lane) * SROW + m];
                    p[0]          += g0 * g1 * xv;     // LDS+FFMA+STS, no races
                    p[ 32 * SROW] += f0 * g1 * xv;
                    p[160 * SROW] += g0 * f1 * xv;
                    p[192 * SROW] += f0 * f1 * xv;
                }
#pragma unroll
            for (int j = 0; j < 4; ++j) { R0[j] = R1[j]; R1[j] = R2[j]; xv0[j] = xv1[j]; }
        }
    }
    __syncthreads();

    // ---- GEMM: out[16 x 64] = as[832 x 16]^T @ W[832 x 64] ----
    // Warps 0..3 compute: (khalf = wid>>1) x (chalf = wid&1).
    // W chunk double-buffered through registers: LDG for kt+1 issued before
    // computing kt, hiding L2 latency.
    int khalf = wid >> 1;
    int chalf = wid & 1;
    int rg = lane >> 3, cp = lane & 7;
    int mb = 4 * rg;
    int cb = chalf * 32 + 4 * cp;
    bool compute = (wid < 4);

    ull acc[2][4];
#pragma unroll
    for (int a = 0; a < 2; ++a)
#pragma unroll
        for (int b = 0; b < 4; ++b) acc[a][b] = pack2(0.f, 0.f);

    const int srow = (tid >> 4);       // 0..15
    const int sc4  = tid & 15;         // float4 col
    float4 wreg[4];
#pragma unroll
    for (int p = 0; p < 4; ++p)
        wreg[p] = reinterpret_cast<const float4*>(weight)[(size_t)(srow + 16 * p) * 16 + sc4];

    for (int kt = 0; kt < 13; ++kt) {
        // stage W chunk from registers (all 256 threads)
#pragma unroll
        for (int p = 0; p < 4; ++p)
            reinterpret_cast<float4*>(ws)[(srow + 16 * p) * 16 + sc4] = wreg[p];
        __syncthreads();
        // prefetch next chunk
        if (kt < 12) {
#pragma unroll
            for (int p = 0; p < 4; ++p)
                wreg[p] = reinterpret_cast<const float4*>(
                    weight)[(size_t)((kt + 1) * 64 + srow + 16 * p) * 16 + sc4];
        }
        bool mine = compute && (khalf ? (kt >= 6) : (kt < 6));
        if (mine) {
            const float* ap = &as[(kt * 64) * SROW + mb];
            const float* wp = &ws[cb];
#pragma unroll 8
            for (int k = 0; k < 64; ++k) {
                ull a0 = *reinterpret_cast<const ull*>(ap);
                ull a1 = *reinterpret_cast<const ull*>(ap + 2);
                ull wq0 = *reinterpret_cast<const ull*>(wp);
                ull wq1 = *reinterpret_cast<const ull*>(wp + 2);
                ap += SROW; wp += OUT_CH;
                float w0, w1, w2, w3;
                unpack2(wq0, w0, w1); unpack2(wq1, w2, w3);
                ull d0 = pack2(w0, w0), d1 = pack2(w1, w1);
                ull d2 = pack2(w2, w2), d3 = pack2(w3, w3);
                fma2(acc[0][0], a0, d0); fma2(acc[1][0], a1, d0);
                fma2(acc[0][1], a0, d1); fma2(acc[1][1], a1, d1);
                fma2(acc[0][2], a0, d2); fma2(acc[1][2], a1, d2);
                fma2(acc[0][3], a0, d3); fma2(acc[1][3], a1, d3);
            }
        }
        __syncthreads();
    }

    // ---- combine k-halves via smem (reuse ws) ----
    ull* red = reinterpret_cast<ull*>(ws);
    if (compute && khalf == 1) {
        int idx = chalf * 32 + lane;
#pragma unroll
        for (int a = 0; a < 2; ++a)
#pragma unroll
            for (int b = 0; b < 4; ++b) red[idx * 8 + a * 4 + b] = acc[a][b];
    }
    __syncthreads();
    if (compute && khalf == 0) {
        int idx = chalf * 32 + lane;
#pragma unroll
        for (int a = 0; a < 2; ++a)
#pragma unroll
            for (int b = 0; b < 4; ++b)
                acc[a][b] = add2(acc[a][b], red[idx * 8 + a * 4 + b]);

        // ---- epilogue: 1/deg scale, + bias, store float4 per row ----
        float bb[4];
#pragma unroll
        for (int q = 0; q < 4; ++q) bb[q] = __ldg(&bias[cb + q]);
#pragma unroll
        for (int p = 0; p < 4; ++p) {
            int n = n0 + mb + p;
            if (n >= N) continue;
            float iv = sinv[mb + p];
            float o[4];
#pragma unroll
            for (int q = 0; q < 4; ++q) {
                float lo_, hi_;
                unpack2(acc[p >> 1][q], lo_, hi_);
                o[q] = ((p & 1) ? hi_ : lo_) * iv + bb[q];
            }
            *reinterpret_cast<float4*>(&out[(size_t)n * OUT_CH + cb]) =
                make_float4(o[0], o[1], o[2], o[3]);
        }
    }
}

// ---------------- launch ----------------
extern "C" void kernel_launch(void* const* d_in, const int* in_sizes, int n_in,
                              void* d_out, int out_size) {
    const float* x      = (const float*)d_in[0];
    const float* pseudo = (const float*)d_in[1];
    const int*   ei     = (const int*)  d_in[2];
    const float* weight = (const float*)d_in[3];
    const float* bias   = (const float*)d_in[4];
    float* out = (float*)d_out;

    int N = in_sizes[0] / IN_CH;
    int E = in_sizes[1] / 2;

    cudaFuncSetAttribute(fused_kernel, cudaFuncAttributeMaxDynamicSharedMemorySize, SMEM_BYTES);

    zero_small_kernel<<<(MAX_N + 255) / 256, 256>>>();
    hist_kernel<<<(E + 255) / 256, 256>>>(ei, E);
    scan_a_kernel<<<NBLK_SC, 256>>>();
    scan_b_kernel<<<1, 256>>>();
    scan_c_kernel<<<NBLK_SC, 256>>>();
    permute_kernel<<<(E + 255) / 256, 256>>>(ei, pseudo, E);
    fused_kernel<<<(N + NPB - 1) / NPB, 256, SMEM_BYTES>>>(x, weight, bias, out, N);
}

// round 13
// speedup vs baseline: 1.4669x; 1.0011x over previous
#include <cuda_runtime.h>
#include <cstdint>

// ---------------- problem constants ----------------
#define IN_CH   32
#define OUT_CH  64
#define KSZ     5
#define KTOTAL  832            // 25*32 + 32 (root rows)
#define MAX_N   50176          // 196 * 256
#define NBLK_SC 196
#define MAX_E   1700000
#define NPB     16             // nodes per block
#define SROW    18             // padded node stride (even: LDS.64 pairs)

// smem: as[832][18] + ws[64][64] + sinv[16]
#define SMEM_FLOATS (KTOTAL * SROW + 64 * OUT_CH + NPB)
#define SMEM_BYTES  (SMEM_FLOATS * 4)     // 76,352 B -> 2 blocks/SM

// ---------------- scratch ----------------
__device__ int    g_deg[MAX_N];
__device__ int    g_cnt[MAX_N];
__device__ int    g_ptr[MAX_N];
__device__ int    g_bsum[256];
__device__ int    g_boff[256];
__device__ float  g_invdeg[MAX_N];
__device__ float4 g_erec[MAX_E];   // {col(int), wib|m<<8 (int), f0, f1}

// ---------------- f32x2 helpers ----------------
typedef unsigned long long ull;
__device__ __forceinline__ ull pack2(float lo, float hi) {
    ull d; asm("mov.b64 %0, {%1, %2};" : "=l"(d) : "f"(lo), "f"(hi)); return d;
}
__device__ __forceinline__ void fma2(ull& c, ull a, ull b) {
    asm("fma.rn.f32x2 %0, %1, %2, %3;" : "=l"(c) : "l"(a), "l"(b), "l"(c));
}
__device__ __forceinline__ ull add2(ull a, ull b) {
    ull d; asm("add.rn.f32x2 %0, %1, %2;" : "=l"(d) : "l"(a), "l"(b)); return d;
}
__device__ __forceinline__ void unpack2(ull d, float& lo, float& hi) {
    asm("mov.b64 {%0, %1}, %2;" : "=f"(lo), "=f"(hi) : "l"(d));
}

// ---------------- k0: zero counters ----------------
__global__ void zero_small_kernel() {
    int i = blockIdx.x * 256 + threadIdx.x;
    if (i < MAX_N) { g_deg[i] = 0; g_cnt[i] = 0; }
}

// ---------------- k1: degree histogram ----------------
__global__ void hist_kernel(const int* __restrict__ ei, int E) {
    int e = blockIdx.x * 256 + threadIdx.x;
    if (e < E) atomicAdd(&g_deg[ei[e]], 1);
}

// ---------------- k2a: per-block sums ----------------
__global__ void scan_a_kernel() {
    __shared__ int s[256];
    int tid = threadIdx.x;
    int i = blockIdx.x * 256 + tid;
    int d = g_deg[i];
    s[tid] = d; __syncthreads();
    for (int off = 128; off > 0; off >>= 1) {
        if (tid < off) s[tid] += s[tid + off];
        __syncthreads();
    }
    if (tid == 0) g_bsum[blockIdx.x] = s[0];
}

// ---------------- k2b: scan of block sums ----------------
__global__ void scan_b_kernel() {
    __shared__ int s[256];
    int tid = threadIdx.x;
    int v = (tid < NBLK_SC) ? g_bsum[tid] : 0;
    s[tid] = v; __syncthreads();
    for (int off = 1; off < 256; off <<= 1) {
        int t = (tid >= off) ? s[tid - off] : 0;
        __syncthreads();
        s[tid] += t;
        __syncthreads();
    }
    if (tid < NBLK_SC) g_boff[tid] = s[tid] - v;
}

// ---------------- k2c: per-block exclusive scan -> g_ptr ----------------
__global__ void scan_c_kernel() {
    __shared__ int s[256];
    int tid = threadIdx.x;
    int i = blockIdx.x * 256 + tid;
    int d = g_deg[i];
    s[tid] = d; __syncthreads();
    for (int off = 1; off < 256; off <<= 1) {
        int t = (tid >= off) ? s[tid - off] : 0;
        __syncthreads();
        s[tid] += t;
        __syncthreads();
    }
    g_ptr[i] = g_boff[blockIdx.x] + s[tid] - d;
    g_invdeg[i] = 1.0f / (float)max(d, 1);
}

// ---------------- k3: permute edges into CSR order ----------------
__global__ void permute_kernel(const int* __restrict__ ei,
                               const float* __restrict__ pseudo,
                               int E) {
    int e = blockIdx.x * 256 + threadIdx.x;
    if (e >= E) return;
    int row = ei[e];
    int col = ei[E + e];
    float2 ps = reinterpret_cast<const float2*>(pseudo)[e];
    float v0 = ps.x * 4.0f;           // (ks - open) = 4, v in [0,4)
    float v1 = ps.y * 4.0f;
    float b0 = floorf(v0), b1 = floorf(v1);
    float f0 = v0 - b0,  f1 = v1 - b1;
    int wib = (int)b0 + KSZ * (int)b1;
    int meta = wib | ((row & (NPB - 1)) << 8);
    int pos = g_ptr[row] + atomicAdd(&g_cnt[row], 1);
    g_erec[pos] = make_float4(__int_as_float(col), __int_as_float(meta), f0, f1);
}

// ---------------- fused: race-free RMW accumulate + f32x2 GEMM ----------------
__global__ __launch_bounds__(256, 2) void fused_kernel(const float* __restrict__ x,
                                                       const float* __restrict__ weight,
                                                       const float* __restrict__ bias,
                                                       float* __restrict__ out,
                                                       int N) {
    extern __shared__ float sm[];
    float* as   = sm;                        // [832][SROW]
    float* ws   = sm + KTOTAL * SROW;        // [64][64]
    float* sinv = ws + 64 * OUT_CH;          // [16]

    int tid  = threadIdx.x;
    int lane = tid & 31;
    int wid  = tid >> 5;
    int n0   = blockIdx.x * NPB;

    // ---- zero spline rows (kg 0..799) ----
    {
        float4 z = make_float4(0.f, 0.f, 0.f, 0.f);
        float4* a4 = reinterpret_cast<float4*>(as);
        for (int i = tid; i < (800 * SROW) / 4; i += 256) a4[i] = z;
    }
    if (tid < NPB) {
        int n = n0 + tid;
        sinv[tid] = (n < N) ? g_invdeg[n] : 1.f;
    }
    // ---- stage x * deg into root rows (kg 800..831) ----
    for (int i = tid; i < NPB * IN_CH; i += 256) {
        int m = i >> 5, ch = i & 31;
        int n = n0 + m;
        float v = 0.f;
        if (n < N) v = x[(size_t)n * IN_CH + ch] * (float)max(g_deg[n], 1);
        as[(800 + ch) * SROW + m] = v;
    }
    __syncthreads();

    // ---- accumulate: warp owns 2 nodes, lane owns channel -> race-free RMW ----
#pragma unroll
    for (int nn = 0; nn < 2; ++nn) {
        int m = wid * 2 + nn;
        int n = n0 + m;
        if (n >= N) continue;
        int lo  = g_ptr[n];
        int hi  = g_ptr[n + 1];
        if (lo >= hi) continue;

        float4 R0[4], R1[4];
        float xv0[4];
#pragma unroll
        for (int j = 0; j < 4; ++j) {
            R0[j] = (lo + j     < hi) ? __ldg(&g_erec[lo + j])     : make_float4(0.f,0.f,0.f,0.f);
            R1[j] = (lo + 4 + j < hi) ? __ldg(&g_erec[lo + 4 + j]) : make_float4(0.f,0.f,0.f,0.f);
        }
#pragma unroll
        for (int j = 0; j < 4; ++j)
            xv0[j] = (lo + j < hi)
                   ? __ldg(&x[(size_t)__float_as_int(R0[j].x) * IN_CH + lane]) : 0.f;

        for (int e = lo; e < hi; e += 4) {
            float xv1[4];
#pragma unroll
            for (int j = 0; j < 4; ++j)
                xv1[j] = (e + 4 + j < hi)
                       ? __ldg(&x[(size_t)__float_as_int(R1[j].x) * IN_CH + lane]) : 0.f;
            float4 R2[4];
#pragma unroll
            for (int j = 0; j < 4; ++j)
                R2[j] = (e + 8 + j < hi) ? __ldg(&g_erec[e + 8 + j])
                                         : make_float4(0.f,0.f,0.f,0.f);
            int cnt = hi - e; if (cnt > 4) cnt = 4;
#pragma unroll
            for (int j = 0; j < 4; ++j)
                if (j < cnt) {
                    int  wib  = __float_as_int(R0[j].y) & 255;
                    float f0 = R0[j].z, f1 = R0[j].w;
                    float g0 = 1.f - f0, g1 = 1.f - f1;
                    float xv = xv0[j];
                    float* p = &as[(wib * 32 + lane) * SROW + m];
                    p[0]          += g0 * g1 * xv;     // LDS+FFMA+STS, no races
                    p[ 32 * SROW] += f0 * g1 * xv;
                    p[160 * SROW] += g0 * f1 * xv;
                    p[192 * SROW] += f0 * f1 * xv;
                }
#pragma unroll
            for (int j = 0; j < 4; ++j) { R0[j] = R1[j]; R1[j] = R2[j]; xv0[j] = xv1[j]; }
        }
    }
    __syncthreads();

    // ---- GEMM: out[16 x 64] = as[832 x 16]^T @ W[832 x 64] ----
    // Warps 0..3 compute: (khalf = wid>>1) x (chalf = wid&1).
    // W chunk double-buffered through registers: LDG for kt+1 issued before
    // computing kt, hiding L2 latency.
    int khalf = wid >> 1;
    int chalf = wid & 1;
    int rg = lane >> 3, cp = lane & 7;
    int mb = 4 * rg;
    int cb = chalf * 32 + 4 * cp;
    bool compute = (wid < 4);

    ull acc[2][4];
#pragma unroll
    for (int a = 0; a < 2; ++a)
#pragma unroll
        for (int b = 0; b < 4; ++b) acc[a][b] = pack2(0.f, 0.f);

    const int srow = (tid >> 4);       // 0..15
    const int sc4  = tid & 15;         // float4 col
    float4 wreg[4];
#pragma unroll
    for (int p = 0; p < 4; ++p)
        wreg[p] = reinterpret_cast<const float4*>(weight)[(size_t)(srow + 16 * p) * 16 + sc4];

    for (int kt = 0; kt < 13; ++kt) {
        // stage W chunk from registers (all 256 threads)
#pragma unroll
        for (int p = 0; p < 4; ++p)
            reinterpret_cast<float4*>(ws)[(srow + 16 * p) * 16 + sc4] = wreg[p];
        __syncthreads();
        // prefetch next chunk
        if (kt < 12) {
#pragma unroll
            for (int p = 0; p < 4; ++p)
                wreg[p] = reinterpret_cast<const float4*>(
                    weight)[(size_t)((kt + 1) * 64 + srow + 16 * p) * 16 + sc4];
        }
        bool mine = compute && (khalf ? (kt >= 6) : (kt < 6));
        if (mine) {
            const float* ap = &as[(kt * 64) * SROW + mb];
            const float* wp = &ws[cb];
#pragma unroll 8
            for (int k = 0; k < 64; ++k) {
                ull a0 = *reinterpret_cast<const ull*>(ap);
                ull a1 = *reinterpret_cast<const ull*>(ap + 2);
                ull wq0 = *reinterpret_cast<const ull*>(wp);
                ull wq1 = *reinterpret_cast<const ull*>(wp + 2);
                ap += SROW; wp += OUT_CH;
                float w0, w1, w2, w3;
                unpack2(wq0, w0, w1); unpack2(wq1, w2, w3);
                ull d0 = pack2(w0, w0), d1 = pack2(w1, w1);
                ull d2 = pack2(w2, w2), d3 = pack2(w3, w3);
                fma2(acc[0][0], a0, d0); fma2(acc[1][0], a1, d0);
                fma2(acc[0][1], a0, d1); fma2(acc[1][1], a1, d1);
                fma2(acc[0][2], a0, d2); fma2(acc[1][2], a1, d2);
                fma2(acc[0][3], a0, d3); fma2(acc[1][3], a1, d3);
            }
        }
        __syncthreads();
    }

    // ---- combine k-halves via smem (reuse ws) ----
    ull* red = reinterpret_cast<ull*>(ws);
    if (compute && khalf == 1) {
        int idx = chalf * 32 + lane;
#pragma unroll
        for (int a = 0; a < 2; ++a)
#pragma unroll
            for (int b = 0; b < 4; ++b) red[idx * 8 + a * 4 + b] = acc[a][b];
    }
    __syncthreads();
    if (compute && khalf == 0) {
        int idx = chalf * 32 + lane;
#pragma unroll
        for (int a = 0; a < 2; ++a)
#pragma unroll
            for (int b = 0; b < 4; ++b)
                acc[a][b] = add2(acc[a][b], red[idx * 8 + a * 4 + b]);

        // ---- epilogue: 1/deg scale, + bias, store float4 per row ----
        float bb[4];
#pragma unroll
        for (int q = 0; q < 4; ++q) bb[q] = __ldg(&bias[cb + q]);
#pragma unroll
        for (int p = 0; p < 4; ++p) {
            int n = n0 + mb + p;
            if (n >= N) continue;
            float iv = sinv[mb + p];
            float o[4];
#pragma unroll
            for (int q = 0; q < 4; ++q) {
                float lo_, hi_;
                unpack2(acc[p >> 1][q], lo_, hi_);
                o[q] = ((p & 1) ? hi_ : lo_) * iv + bb[q];
            }
            *reinterpret_cast<float4*>(&out[(size_t)n * OUT_CH + cb]) =
                make_float4(o[0], o[1], o[2], o[3]);
        }
    }
}

// ---------------- launch ----------------
extern "C" void kernel_launch(void* const* d_in, const int* in_sizes, int n_in,
                              void* d_out, int out_size) {
    const float* x      = (const float*)d_in[0];
    const float* pseudo = (const float*)d_in[1];
    const int*   ei     = (const int*)  d_in[2];
    const float* weight = (const float*)d_in[3];
    const float* bias   = (const float*)d_in[4];
    float* out = (float*)d_out;

    int N = in_sizes[0] / IN_CH;
    int E = in_sizes[1] / 2;

    cudaFuncSetAttribute(fused_kernel, cudaFuncAttributeMaxDynamicSharedMemorySize, SMEM_BYTES);

    zero_small_kernel<<<(MAX_N + 255) / 256, 256>>>();
    hist_kernel<<<(E + 255) / 256, 256>>>(ei, E);
    scan_a_kernel<<<NBLK_SC, 256>>>();
    scan_b_kernel<<<1, 256>>>();
    scan_c_kernel<<<NBLK_SC, 256>>>();
    permute_kernel<<<(E + 255) / 256, 256>>>(ei, pseudo, E);
    fused_kernel<<<(N + NPB - 1) / NPB, 256, SMEM_BYTES>>>(x, weight, bias, out, N);
}